// round 2
// baseline (speedup 1.0000x reference)
#include <cuda_runtime.h>

#define N_USERS 50000
#define N_ITEMS 30000
#define N_ENT   100000
#define N_REL   8
#define E_KG    250000
#define E_UI    1000000
#define DIMF    128
#define KG_CNT  (N_REL*N_ENT)        /* 800000 */
#define TOT_CNT (KG_CNT + N_USERS)   /* 850000 */
#define KG_EDGE (N_REL*E_KG)         /* 2000000 */
#define TOT_EDGE (KG_EDGE + E_UI)    /* 3000000 */
#define SCAN_B  1024
#define NBLK    ((TOT_CNT + SCAN_B - 1)/SCAN_B)  /* 831 */

// ---------------- scratch (static device globals; no allocation) ------------
__device__ float g_ent0[(size_t)N_ENT*DIMF];    // 51.2 MB
__device__ float g_ent1[(size_t)N_ENT*DIMF];    // 51.2 MB
__device__ float g_entres[(size_t)N_ENT*DIMF];  // 51.2 MB
__device__ int   g_cnt[TOT_CNT];
__device__ int   g_rowptr[TOT_CNT+1];
__device__ int   g_cursor[TOT_CNT];
__device__ int   g_col[TOT_EDGE];
__device__ int   g_bsum[NBLK];
__device__ float g_imean[DIMF];

// ---------------- CSR build -------------------------------------------------
__global__ void k_zero() {
    int i = blockIdx.x*blockDim.x + threadIdx.x;
    for (int t = i; t < TOT_CNT; t += gridDim.x*blockDim.x) g_cnt[t] = 0;
    if (i < DIMF) g_imean[i] = 0.f;
}

__global__ void k_count(const int* __restrict__ kg_dst, const int* __restrict__ ui_dst) {
    int tid = blockIdx.x*blockDim.x + threadIdx.x;
    if (tid < KG_EDGE) {
        int r = tid / E_KG;
        atomicAdd(&g_cnt[r*N_ENT + __ldg(&kg_dst[tid])], 1);
    } else if (tid < TOT_EDGE) {
        atomicAdd(&g_cnt[KG_CNT + __ldg(&ui_dst[tid - KG_EDGE])], 1);
    }
}

__global__ void k_scan1() {
    __shared__ int sh[SCAN_B];
    int i = blockIdx.x*SCAN_B + threadIdx.x;
    int v = (i < TOT_CNT) ? g_cnt[i] : 0;
    sh[threadIdx.x] = v;
    __syncthreads();
    #pragma unroll
    for (int off = 1; off < SCAN_B; off <<= 1) {
        int t = (threadIdx.x >= off) ? sh[threadIdx.x - off] : 0;
        __syncthreads();
        sh[threadIdx.x] += t;
        __syncthreads();
    }
    if (i < TOT_CNT) g_rowptr[i] = sh[threadIdx.x] - v;   // exclusive
    if (threadIdx.x == SCAN_B-1) g_bsum[blockIdx.x] = sh[SCAN_B-1];
}

__global__ void k_scan2() {
    __shared__ int sh[SCAN_B];
    int t = threadIdx.x;
    int v = (t < NBLK) ? g_bsum[t] : 0;
    sh[t] = v;
    __syncthreads();
    #pragma unroll
    for (int off = 1; off < SCAN_B; off <<= 1) {
        int u = (t >= off) ? sh[t - off] : 0;
        __syncthreads();
        sh[t] += u;
        __syncthreads();
    }
    if (t < NBLK) g_bsum[t] = sh[t] - v;                  // exclusive
}

__global__ void k_scan3() {
    int i = blockIdx.x*blockDim.x + threadIdx.x;
    if (i < TOT_CNT) {
        int v = g_rowptr[i] + g_bsum[i / SCAN_B];
        g_rowptr[i] = v;
        g_cursor[i] = v;
    }
    if (i == TOT_CNT) g_rowptr[TOT_CNT] = TOT_EDGE;
}

__global__ void k_fill(const int* __restrict__ kg_src, const int* __restrict__ kg_dst,
                       const int* __restrict__ ui_src, const int* __restrict__ ui_dst) {
    int tid = blockIdx.x*blockDim.x + threadIdx.x;
    if (tid < KG_EDGE) {
        int r = tid / E_KG;
        int pos = atomicAdd(&g_cursor[r*N_ENT + __ldg(&kg_dst[tid])], 1);
        g_col[pos] = __ldg(&kg_src[tid]);
    } else if (tid < TOT_EDGE) {
        int t = tid - KG_EDGE;
        int pos = atomicAdd(&g_cursor[KG_CNT + __ldg(&ui_dst[t])], 1);
        g_col[pos] = __ldg(&ui_src[t]);
    }
}

// ---------------- layer 0: per-relation 16-dim slice seg_mean ---------------
// warp per destination entity; lanes 0-15 / 16-31 process alternate neighbors
__global__ void k_layer0(const float* __restrict__ all_embed) {
    int d = blockIdx.x*(blockDim.x/32) + (threadIdx.x >> 5);
    if (d >= N_ENT) return;
    int lane = threadIdx.x & 31;
    int dim  = lane & 15;
    int half = lane >> 4;
    #pragma unroll
    for (int r = 0; r < N_REL; r++) {
        int base = r*N_ENT + d;
        int s = __ldg(&g_rowptr[base]), e = __ldg(&g_rowptr[base+1]);
        float acc = 0.f;
        for (int j = s + half; j < e; j += 2)
            acc += __ldg(&all_embed[__ldg(&g_col[j])*DIMF + r*16 + dim]);
        acc += __shfl_xor_sync(0xffffffffu, acc, 16);
        if (half == 0) {
            float v = acc / fmaxf((float)(e - s), 1.f);
            int o = d*DIMF + r*16 + dim;
            g_ent0[o]   = v;
            g_entres[o] = v;
        }
    }
}

// ---------------- hop: out[d] = sum_r mean_r(in[src]); ent_res += out -------
// warp per destination; each lane owns 4 dims (float4)
__global__ void k_hop(int phase) {
    const float* __restrict__ in = phase ? g_ent1 : g_ent0;
    float* __restrict__ out      = phase ? g_ent0 : g_ent1;
    int d = blockIdx.x*(blockDim.x/32) + (threadIdx.x >> 5);
    if (d >= N_ENT) return;
    int lane = threadIdx.x & 31;
    float4 acc = make_float4(0.f,0.f,0.f,0.f);
    #pragma unroll
    for (int r = 0; r < N_REL; r++) {
        int base = r*N_ENT + d;
        int s = __ldg(&g_rowptr[base]), e = __ldg(&g_rowptr[base+1]);
        float4 rs = make_float4(0.f,0.f,0.f,0.f);
        for (int j = s; j < e; j++) {
            const float4 v = __ldg((const float4*)&in[__ldg(&g_col[j])*DIMF + lane*4]);
            rs.x += v.x; rs.y += v.y; rs.z += v.z; rs.w += v.w;
        }
        float inv = 1.f / fmaxf((float)(e - s), 1.f);
        acc.x += rs.x*inv; acc.y += rs.y*inv; acc.z += rs.z*inv; acc.w += rs.w*inv;
    }
    *(float4*)&out[d*DIMF + lane*4] = acc;
    float4* rr = (float4*)&g_entres[d*DIMF + lane*4];
    float4 c = *rr;
    c.x += acc.x; c.y += acc.y; c.z += acc.z; c.w += acc.w;
    *rr = c;
}

// ---------------- item_mean over ent_res[:N_ITEMS] --------------------------
__global__ void k_imean() {
    int t = threadIdx.x;   // 128 threads
    float acc = 0.f;
    for (int row = blockIdx.x; row < N_ITEMS; row += gridDim.x)
        acc += g_entres[row*DIMF + t];
    atomicAdd(&g_imean[t], acc * (1.f / N_ITEMS));
}

// ---------------- item_out = ent_res[:N_ITEMS] + item_cf --------------------
__global__ void k_itemout(const float* __restrict__ cf, float* __restrict__ out) {
    int tid = blockIdx.x*blockDim.x + threadIdx.x;
    if (tid < N_ITEMS*DIMF)
        out[tid] = g_entres[tid] + __ldg(&cf[N_USERS*DIMF + tid]);
}

// ---------------- user aggregation + fused attention epilogue ---------------
// warp per user; lane owns dims [4*lane, 4*lane+4); relation r = lanes 4r..4r+3
__global__ void k_user(const float* __restrict__ cf, float* __restrict__ out_user) {
    int u = blockIdx.x*(blockDim.x/32) + (threadIdx.x >> 5);
    if (u >= N_USERS) return;
    int lane = threadIdx.x & 31;
    int base = KG_CNT + u;
    int s = __ldg(&g_rowptr[base]), e = __ldg(&g_rowptr[base+1]);
    float4 sf  = make_float4(0.f,0.f,0.f,0.f);
    float4 sf0 = make_float4(0.f,0.f,0.f,0.f);
    for (int j = s; j < e; j++) {
        int it = __ldg(&g_col[j]);
        const float4 a = __ldg((const float4*)&g_entres[it*DIMF + lane*4]);
        const float4 b = __ldg((const float4*)&cf[(N_USERS + it)*DIMF + lane*4]);
        sf.x  += a.x; sf.y  += a.y; sf.z  += a.z; sf.w  += a.w;
        sf0.x += b.x; sf0.y += b.y; sf0.z += b.z; sf0.w += b.w;
    }
    float inv = 1.f / fmaxf((float)(e - s), 1.f);
    float4 uf  = make_float4(sf.x*inv,  sf.y*inv,  sf.z*inv,  sf.w*inv);
    float4 uf0 = make_float4(sf0.x*inv, sf0.y*inv, sf0.z*inv, sf0.w*inv);
    const float4 ucf = __ldg((const float4*)&cf[u*DIMF + lane*4]);
    const float4 im  = *(const float4*)&g_imean[lane*4];

    float ua = uf.x*ucf.x + uf.y*ucf.y + uf.z*ucf.z + uf.w*ucf.w;
    float ma = im.x*ucf.x + im.y*ucf.y + im.z*ucf.z + im.w*ucf.w;
    // reduce over the 4-lane group that forms one relation (16 dims)
    ua += __shfl_xor_sync(0xffffffffu, ua, 1);
    ua += __shfl_xor_sync(0xffffffffu, ua, 2);
    ma += __shfl_xor_sync(0xffffffffu, ma, 1);
    ma += __shfl_xor_sync(0xffffffffu, ma, 2);
    ua = fmaxf(ua, 0.f) + 1e-10f;
    ma = fmaxf(ma, 0.f) + 1e-8f;
    float att = fmaxf(ua/ma - 1.f, 0.f) + 0.01f;   // K_ATT = 1.0
    float score = tanhf(att);

    float4 o;
    o.x = score*uf.x + uf0.x + ucf.x;
    o.y = score*uf.y + uf0.y + ucf.y;
    o.z = score*uf.z + uf0.z + ucf.z;
    o.w = score*uf.w + uf0.w + ucf.w;
    *(float4*)&out_user[u*DIMF + lane*4] = o;
}

// ---------------- launch ----------------------------------------------------
extern "C" void kernel_launch(void* const* d_in, const int* in_sizes, int n_in,
                              void* d_out, int out_size) {
    const float* all_embed    = (const float*)d_in[0];
    const float* all_embed_cf = (const float*)d_in[1];
    const int*   kg_src       = (const int*)d_in[2];
    const int*   kg_dst       = (const int*)d_in[3];
    const int*   ui_src_item  = (const int*)d_in[4];
    const int*   ui_dst_user  = (const int*)d_in[5];
    float* out = (float*)d_out;
    float* out_item = out;                        // [N_ITEMS, 128]
    float* out_user = out + (size_t)N_ITEMS*DIMF; // [N_USERS, 128]

    const int T = 256;
    // CSR build
    k_zero<<<1024, T>>>();
    k_count<<<(TOT_EDGE + T - 1)/T, T>>>(kg_dst, ui_dst_user);
    k_scan1<<<NBLK, SCAN_B>>>();
    k_scan2<<<1, SCAN_B>>>();
    k_scan3<<<(TOT_CNT + T)/T, T>>>();
    k_fill<<<(TOT_EDGE + T - 1)/T, T>>>(kg_src, kg_dst, ui_src_item, ui_dst_user);

    // KG propagation
    int entWarpBlocks = (N_ENT + (T/32) - 1) / (T/32);   // warp per entity
    k_layer0<<<entWarpBlocks, T>>>(all_embed);
    k_hop<<<entWarpBlocks, T>>>(0);   // ent0 -> ent1, ent_res +=
    k_hop<<<entWarpBlocks, T>>>(1);   // ent1 -> ent0, ent_res +=

    // epilogues
    k_imean<<<264, DIMF>>>();
    k_itemout<<<(N_ITEMS*DIMF + T - 1)/T, T>>>(all_embed_cf, out_item);
    int userWarpBlocks = (N_USERS + (T/32) - 1) / (T/32);
    k_user<<<userWarpBlocks, T>>>(all_embed_cf, out_user);
}

// round 3
// speedup vs baseline: 1.3602x; 1.3602x over previous
#include <cuda_runtime.h>

#define N_USERS 50000
#define N_ITEMS 30000
#define N_ENT   100000
#define N_REL   8
#define E_KG    250000
#define E_UI    1000000
#define DIMF    128
#define KG_CNT  (N_REL*N_ENT)        /* 800000  KG rows, laid out [d][r] */
#define TOT_CNT (KG_CNT + N_USERS)   /* 850000 */
#define KG_EDGE (N_REL*E_KG)         /* 2000000 */
#define TOT_EDGE (KG_EDGE + E_UI)    /* 3000000 */
#define SCAN_B  1024
#define NBLK    ((TOT_CNT + SCAN_B - 1)/SCAN_B)  /* 831 */

// ---------------- scratch (static device globals; no allocation) ------------
__device__ float g_ent0[(size_t)N_ENT*DIMF];      // 51.2 MB  layer0 output
__device__ float g_ent1[(size_t)N_ENT*DIMF];      // 51.2 MB  hop1 output
__device__ float g_entres[(size_t)N_ITEMS*DIMF];  // 15.4 MB  item slice of ent_res
__device__ int   g_cnt[TOT_CNT];
__device__ int   g_rowptr[TOT_CNT+1];
__device__ int   g_cursor[TOT_CNT];
__device__ int   g_col[TOT_EDGE];
__device__ int   g_bsum[NBLK];
__device__ float g_imean[DIMF];

// KG row index: entity-major so the 9 rowptrs per entity are contiguous
__device__ __forceinline__ int kgrow(int d, int r) { return d*N_REL + r; }

// ---------------- CSR build -------------------------------------------------
__global__ void k_zero() {
    int i = blockIdx.x*blockDim.x + threadIdx.x;
    for (int t = i; t < TOT_CNT; t += gridDim.x*blockDim.x) g_cnt[t] = 0;
    if (i < DIMF) g_imean[i] = 0.f;
}

__global__ void k_count(const int* __restrict__ kg_dst, const int* __restrict__ ui_dst) {
    int tid = blockIdx.x*blockDim.x + threadIdx.x;
    if (tid < KG_EDGE) {
        int r = tid / E_KG;
        atomicAdd(&g_cnt[kgrow(__ldg(&kg_dst[tid]), r)], 1);
    } else if (tid < TOT_EDGE) {
        atomicAdd(&g_cnt[KG_CNT + __ldg(&ui_dst[tid - KG_EDGE])], 1);
    }
}

__global__ void k_scan1() {
    __shared__ int sh[SCAN_B];
    int i = blockIdx.x*SCAN_B + threadIdx.x;
    int v = (i < TOT_CNT) ? g_cnt[i] : 0;
    sh[threadIdx.x] = v;
    __syncthreads();
    #pragma unroll
    for (int off = 1; off < SCAN_B; off <<= 1) {
        int t = (threadIdx.x >= off) ? sh[threadIdx.x - off] : 0;
        __syncthreads();
        sh[threadIdx.x] += t;
        __syncthreads();
    }
    if (i < TOT_CNT) g_rowptr[i] = sh[threadIdx.x] - v;   // exclusive within block
    if (threadIdx.x == SCAN_B-1) g_bsum[blockIdx.x] = sh[SCAN_B-1];
}

__global__ void k_scan2() {
    __shared__ int sh[SCAN_B];
    int t = threadIdx.x;
    int v = (t < NBLK) ? g_bsum[t] : 0;
    sh[t] = v;
    __syncthreads();
    #pragma unroll
    for (int off = 1; off < SCAN_B; off <<= 1) {
        int u = (t >= off) ? sh[t - off] : 0;
        __syncthreads();
        sh[t] += u;
        __syncthreads();
    }
    if (t < NBLK) g_bsum[t] = sh[t] - v;                  // exclusive
}

__global__ void k_scan3() {
    int i = blockIdx.x*blockDim.x + threadIdx.x;
    if (i < TOT_CNT) {
        int v = g_rowptr[i] + g_bsum[i / SCAN_B];
        g_rowptr[i] = v;
        g_cursor[i] = v;
    }
    if (i == TOT_CNT) g_rowptr[TOT_CNT] = TOT_EDGE;
}

__global__ void k_fill(const int* __restrict__ kg_src, const int* __restrict__ kg_dst,
                       const int* __restrict__ ui_src, const int* __restrict__ ui_dst) {
    int tid = blockIdx.x*blockDim.x + threadIdx.x;
    if (tid < KG_EDGE) {
        int r = tid / E_KG;
        int pos = atomicAdd(&g_cursor[kgrow(__ldg(&kg_dst[tid]), r)], 1);
        g_col[pos] = __ldg(&kg_src[tid]);
    } else if (tid < TOT_EDGE) {
        int t = tid - KG_EDGE;
        int pos = atomicAdd(&g_cursor[KG_CNT + __ldg(&ui_dst[t])], 1);
        g_col[pos] = __ldg(&ui_src[t]);
    }
}

// ---------------- layer 0: per-relation 16-dim slice seg_mean ---------------
// warp per destination entity; lanes 0-15 / 16-31 process alternate neighbors
__global__ void k_layer0(const float* __restrict__ all_embed) {
    int d = blockIdx.x*(blockDim.x/32) + (threadIdx.x >> 5);
    if (d >= N_ENT) return;
    int lane = threadIdx.x & 31;
    int dim  = lane & 15;
    int half = lane >> 4;
    #pragma unroll
    for (int r = 0; r < N_REL; r++) {
        int base = kgrow(d, r);
        int s = __ldg(&g_rowptr[base]), e = __ldg(&g_rowptr[base+1]);
        float acc = 0.f;
        for (int j = s + half; j < e; j += 2)
            acc += __ldg(&all_embed[__ldg(&g_col[j])*DIMF + r*16 + dim]);
        acc += __shfl_xor_sync(0xffffffffu, acc, 16);
        if (half == 0)
            g_ent0[d*DIMF + r*16 + dim] = acc / fmaxf((float)(e - s), 1.f);
    }
}

// ---------------- hop1: g_ent1[d] = sum_r mean_r(g_ent0[src]), all entities -
__global__ void k_hop1() {
    int d = blockIdx.x*(blockDim.x/32) + (threadIdx.x >> 5);
    if (d >= N_ENT) return;
    int lane = threadIdx.x & 31;
    float4 acc = make_float4(0.f,0.f,0.f,0.f);
    #pragma unroll
    for (int r = 0; r < N_REL; r++) {
        int base = kgrow(d, r);
        int s = __ldg(&g_rowptr[base]), e = __ldg(&g_rowptr[base+1]);
        float4 rs = make_float4(0.f,0.f,0.f,0.f);
        for (int j = s; j < e; j++) {
            const float4 v = __ldg((const float4*)&g_ent0[__ldg(&g_col[j])*DIMF + lane*4]);
            rs.x += v.x; rs.y += v.y; rs.z += v.z; rs.w += v.w;
        }
        float inv = 1.f / fmaxf((float)(e - s), 1.f);
        acc.x += rs.x*inv; acc.y += rs.y*inv; acc.z += rs.z*inv; acc.w += rs.w*inv;
    }
    *(float4*)&g_ent1[d*DIMF + lane*4] = acc;
}

// ---------------- hop2 (items only) + entres + item_out fusion ---------------
// entres[d] = ent0[d] + ent1[d] + sum_r mean_r(ent1[src]);  out_item = entres + item_cf
__global__ void k_hop2_items(const float* __restrict__ cf, float* __restrict__ out_item) {
    int d = blockIdx.x*(blockDim.x/32) + (threadIdx.x >> 5);
    if (d >= N_ITEMS) return;
    int lane = threadIdx.x & 31;
    float4 acc = make_float4(0.f,0.f,0.f,0.f);
    #pragma unroll
    for (int r = 0; r < N_REL; r++) {
        int base = kgrow(d, r);
        int s = __ldg(&g_rowptr[base]), e = __ldg(&g_rowptr[base+1]);
        float4 rs = make_float4(0.f,0.f,0.f,0.f);
        for (int j = s; j < e; j++) {
            const float4 v = __ldg((const float4*)&g_ent1[__ldg(&g_col[j])*DIMF + lane*4]);
            rs.x += v.x; rs.y += v.y; rs.z += v.z; rs.w += v.w;
        }
        float inv = 1.f / fmaxf((float)(e - s), 1.f);
        acc.x += rs.x*inv; acc.y += rs.y*inv; acc.z += rs.z*inv; acc.w += rs.w*inv;
    }
    int o = d*DIMF + lane*4;
    const float4 e0 = *(const float4*)&g_ent0[o];
    const float4 e1 = *(const float4*)&g_ent1[o];
    float4 res;
    res.x = acc.x + e0.x + e1.x;
    res.y = acc.y + e0.y + e1.y;
    res.z = acc.z + e0.z + e1.z;
    res.w = acc.w + e0.w + e1.w;
    *(float4*)&g_entres[o] = res;
    const float4 c = __ldg((const float4*)&cf[(size_t)(N_USERS + d)*DIMF + lane*4]);
    float4 oi;
    oi.x = res.x + c.x; oi.y = res.y + c.y; oi.z = res.z + c.z; oi.w = res.w + c.w;
    *(float4*)&out_item[o] = oi;
}

// ---------------- item_mean over g_entres -----------------------------------
__global__ void k_imean() {
    int t = threadIdx.x;   // 128 threads
    float acc = 0.f;
    for (int row = blockIdx.x; row < N_ITEMS; row += gridDim.x)
        acc += g_entres[row*DIMF + t];
    atomicAdd(&g_imean[t], acc * (1.f / N_ITEMS));
}

// ---------------- user aggregation + fused attention epilogue ---------------
// warp per user; lane owns dims [4*lane, 4*lane+4); relation r = lanes 4r..4r+3
__global__ void k_user(const float* __restrict__ cf, float* __restrict__ out_user) {
    int u = blockIdx.x*(blockDim.x/32) + (threadIdx.x >> 5);
    if (u >= N_USERS) return;
    int lane = threadIdx.x & 31;
    int base = KG_CNT + u;
    int s = __ldg(&g_rowptr[base]), e = __ldg(&g_rowptr[base+1]);
    float4 sf  = make_float4(0.f,0.f,0.f,0.f);
    float4 sf0 = make_float4(0.f,0.f,0.f,0.f);
    for (int j = s; j < e; j++) {
        int it = __ldg(&g_col[j]);
        const float4 a = __ldg((const float4*)&g_entres[it*DIMF + lane*4]);
        const float4 b = __ldg((const float4*)&cf[(size_t)(N_USERS + it)*DIMF + lane*4]);
        sf.x  += a.x; sf.y  += a.y; sf.z  += a.z; sf.w  += a.w;
        sf0.x += b.x; sf0.y += b.y; sf0.z += b.z; sf0.w += b.w;
    }
    float inv = 1.f / fmaxf((float)(e - s), 1.f);
    float4 uf  = make_float4(sf.x*inv,  sf.y*inv,  sf.z*inv,  sf.w*inv);
    float4 uf0 = make_float4(sf0.x*inv, sf0.y*inv, sf0.z*inv, sf0.w*inv);
    const float4 ucf = __ldg((const float4*)&cf[(size_t)u*DIMF + lane*4]);
    const float4 im  = *(const float4*)&g_imean[lane*4];

    float ua = uf.x*ucf.x + uf.y*ucf.y + uf.z*ucf.z + uf.w*ucf.w;
    float ma = im.x*ucf.x + im.y*ucf.y + im.z*ucf.z + im.w*ucf.w;
    // reduce over the 4-lane group forming one relation (16 dims)
    ua += __shfl_xor_sync(0xffffffffu, ua, 1);
    ua += __shfl_xor_sync(0xffffffffu, ua, 2);
    ma += __shfl_xor_sync(0xffffffffu, ma, 1);
    ma += __shfl_xor_sync(0xffffffffu, ma, 2);
    ua = fmaxf(ua, 0.f) + 1e-10f;
    ma = fmaxf(ma, 0.f) + 1e-8f;
    float att = fmaxf(ua/ma - 1.f, 0.f) + 0.01f;   // K_ATT = 1.0
    float score = tanhf(att);

    float4 o;
    o.x = score*uf.x + uf0.x + ucf.x;
    o.y = score*uf.y + uf0.y + ucf.y;
    o.z = score*uf.z + uf0.z + ucf.z;
    o.w = score*uf.w + uf0.w + ucf.w;
    *(float4*)&out_user[(size_t)u*DIMF + lane*4] = o;
}

// ---------------- launch ----------------------------------------------------
extern "C" void kernel_launch(void* const* d_in, const int* in_sizes, int n_in,
                              void* d_out, int out_size) {
    const float* all_embed    = (const float*)d_in[0];
    const float* all_embed_cf = (const float*)d_in[1];
    const int*   kg_src       = (const int*)d_in[2];
    const int*   kg_dst       = (const int*)d_in[3];
    const int*   ui_src_item  = (const int*)d_in[4];
    const int*   ui_dst_user  = (const int*)d_in[5];
    float* out = (float*)d_out;
    float* out_item = out;                        // [N_ITEMS, 128]
    float* out_user = out + (size_t)N_ITEMS*DIMF; // [N_USERS, 128]

    const int T = 256;
    // CSR build
    k_zero<<<1024, T>>>();
    k_count<<<(TOT_EDGE + T - 1)/T, T>>>(kg_dst, ui_dst_user);
    k_scan1<<<NBLK, SCAN_B>>>();
    k_scan2<<<1, SCAN_B>>>();
    k_scan3<<<(TOT_CNT + T)/T, T>>>();
    k_fill<<<(TOT_EDGE + T - 1)/T, T>>>(kg_src, kg_dst, ui_src_item, ui_dst_user);

    // KG propagation
    int entWarpBlocks  = (N_ENT   + (T/32) - 1) / (T/32);
    int itemWarpBlocks = (N_ITEMS + (T/32) - 1) / (T/32);
    k_layer0<<<entWarpBlocks, T>>>(all_embed);
    k_hop1<<<entWarpBlocks, T>>>();
    k_hop2_items<<<itemWarpBlocks, T>>>(all_embed_cf, out_item);

    // epilogues
    k_imean<<<264, DIMF>>>();
    int userWarpBlocks = (N_USERS + (T/32) - 1) / (T/32);
    k_user<<<userWarpBlocks, T>>>(all_embed_cf, out_user);
}

// round 5
// speedup vs baseline: 1.6119x; 1.1851x over previous
#include <cuda_runtime.h>
#include <cuda_fp16.h>

#define N_USERS 50000
#define N_ITEMS 30000
#define N_ENT   100000
#define N_REL   8
#define E_KG    250000
#define E_UI    1000000
#define DIMF    128
#define ROWF    192      /* packed user row: 128 fp32 + 128 fp16 = 192 "float slots" */
#define KG_CNT  (N_REL*N_ENT)
#define TOT_CNT (KG_CNT + N_USERS)
#define KG_EDGE (N_REL*E_KG)
#define TOT_EDGE (KG_EDGE + E_UI)
#define SCAN_B  1024
#define NBLK    ((TOT_CNT + SCAN_B - 1)/SCAN_B)

// ---------------- scratch (static device globals; no allocation) ------------
__device__ float g_ent0[(size_t)N_ENT*DIMF];      // 51.2 MB fp32
__device__ float g_ent1[(size_t)N_ENT*DIMF];      // 51.2 MB fp32
// packed per-item row for k_user: 512B fp32 entres + 256B fp16 item_cf
__device__ float g_urow[(size_t)N_ITEMS*ROWF];    // 23.0 MB
__device__ int   g_cnt[TOT_CNT];
__device__ int   g_rowptr[TOT_CNT+1];
__device__ int   g_cursor[TOT_CNT];
__device__ int   g_col[TOT_EDGE];
__device__ int   g_bsum[NBLK];
__device__ float g_imean[DIMF];

__device__ __forceinline__ int kgrow(int d, int r) { return d*N_REL + r; }

__device__ __forceinline__ float4 ldh4(const __half* p) {
    uint2 u = __ldg((const uint2*)p);
    __half2 a = *(__half2*)&u.x, b = *(__half2*)&u.y;
    float2 f0 = __half22float2(a), f1 = __half22float2(b);
    return make_float4(f0.x, f0.y, f1.x, f1.y);
}
__device__ __forceinline__ void sth4(__half* p, float4 v) {
    __half2 a = __floats2half2_rn(v.x, v.y);
    __half2 b = __floats2half2_rn(v.z, v.w);
    uint2 u; u.x = *(unsigned*)&a; u.y = *(unsigned*)&b;
    *(uint2*)p = u;
}

// ---------------- CSR build -------------------------------------------------
__global__ void k_zero() {
    int i = blockIdx.x*blockDim.x + threadIdx.x;
    for (int t = i; t < TOT_CNT; t += gridDim.x*blockDim.x) g_cnt[t] = 0;
    if (i < DIMF) g_imean[i] = 0.f;
}

__global__ void k_count(const int* __restrict__ kg_dst, const int* __restrict__ ui_dst) {
    int tid = blockIdx.x*blockDim.x + threadIdx.x;
    if (tid < KG_EDGE) {
        int r = tid / E_KG;
        atomicAdd(&g_cnt[kgrow(__ldg(&kg_dst[tid]), r)], 1);
    } else if (tid < TOT_EDGE) {
        atomicAdd(&g_cnt[KG_CNT + __ldg(&ui_dst[tid - KG_EDGE])], 1);
    }
}

__global__ void k_scan1() {
    __shared__ int sh[SCAN_B];
    int i = blockIdx.x*SCAN_B + threadIdx.x;
    int v = (i < TOT_CNT) ? g_cnt[i] : 0;
    sh[threadIdx.x] = v;
    __syncthreads();
    #pragma unroll
    for (int off = 1; off < SCAN_B; off <<= 1) {
        int t = (threadIdx.x >= off) ? sh[threadIdx.x - off] : 0;
        __syncthreads();
        sh[threadIdx.x] += t;
        __syncthreads();
    }
    if (i < TOT_CNT) g_rowptr[i] = sh[threadIdx.x] - v;
    if (threadIdx.x == SCAN_B-1) g_bsum[blockIdx.x] = sh[SCAN_B-1];
}

__global__ void k_scan2() {
    __shared__ int sh[SCAN_B];
    int t = threadIdx.x;
    int v = (t < NBLK) ? g_bsum[t] : 0;
    sh[t] = v;
    __syncthreads();
    #pragma unroll
    for (int off = 1; off < SCAN_B; off <<= 1) {
        int u = (t >= off) ? sh[t - off] : 0;
        __syncthreads();
        sh[t] += u;
        __syncthreads();
    }
    if (t < NBLK) g_bsum[t] = sh[t] - v;
}

__global__ void k_scan3() {
    int i = blockIdx.x*blockDim.x + threadIdx.x;
    if (i < TOT_CNT) {
        int v = g_rowptr[i] + g_bsum[i / SCAN_B];
        g_rowptr[i] = v;
        g_cursor[i] = v;
    }
    if (i == TOT_CNT) g_rowptr[TOT_CNT] = TOT_EDGE;
}

__global__ void k_fill(const int* __restrict__ kg_src, const int* __restrict__ kg_dst,
                       const int* __restrict__ ui_src, const int* __restrict__ ui_dst) {
    int tid = blockIdx.x*blockDim.x + threadIdx.x;
    if (tid < KG_EDGE) {
        int r = tid / E_KG;
        int pos = atomicAdd(&g_cursor[kgrow(__ldg(&kg_dst[tid]), r)], 1);
        g_col[pos] = __ldg(&kg_src[tid]);
    } else if (tid < TOT_EDGE) {
        int t = tid - KG_EDGE;
        int pos = atomicAdd(&g_cursor[KG_CNT + __ldg(&ui_dst[t])], 1);
        g_col[pos] = __ldg(&ui_src[t]);
    }
}

// ---------------- layer 0 ----------------------------------------------------
__global__ void k_layer0(const float* __restrict__ all_embed) {
    int d = blockIdx.x*(blockDim.x/32) + (threadIdx.x >> 5);
    if (d >= N_ENT) return;
    int lane = threadIdx.x & 31;
    int dim  = lane & 15;
    int half = lane >> 4;
    #pragma unroll
    for (int r = 0; r < N_REL; r++) {
        int base = kgrow(d, r);
        int s = __ldg(&g_rowptr[base]), e = __ldg(&g_rowptr[base+1]);
        float acc = 0.f;
        for (int j = s + half; j < e; j += 2)
            acc += __ldg(&all_embed[__ldg(&g_col[j])*DIMF + r*16 + dim]);
        acc += __shfl_xor_sync(0xffffffffu, acc, 16);
        if (half == 0)
            g_ent0[d*DIMF + r*16 + dim] = acc / fmaxf((float)(e - s), 1.f);
    }
}

// ---------------- hop1: ent1[d] = sum_r mean_r(ent0[src]) --------------------
__global__ void k_hop1() {
    int d = blockIdx.x*(blockDim.x/32) + (threadIdx.x >> 5);
    if (d >= N_ENT) return;
    int lane = threadIdx.x & 31;
    float4 acc = make_float4(0.f,0.f,0.f,0.f);
    #pragma unroll
    for (int r = 0; r < N_REL; r++) {
        int base = kgrow(d, r);
        int s = __ldg(&g_rowptr[base]), e = __ldg(&g_rowptr[base+1]);
        float4 r0 = make_float4(0.f,0.f,0.f,0.f);
        float4 r1 = make_float4(0.f,0.f,0.f,0.f);
        int j = s;
        for (; j + 1 < e; j += 2) {
            int c0 = __ldg(&g_col[j]), c1 = __ldg(&g_col[j+1]);
            float4 v0 = __ldg((const float4*)&g_ent0[c0*DIMF + lane*4]);
            float4 v1 = __ldg((const float4*)&g_ent0[c1*DIMF + lane*4]);
            r0.x += v0.x; r0.y += v0.y; r0.z += v0.z; r0.w += v0.w;
            r1.x += v1.x; r1.y += v1.y; r1.z += v1.z; r1.w += v1.w;
        }
        if (j < e) {
            float4 v = __ldg((const float4*)&g_ent0[__ldg(&g_col[j])*DIMF + lane*4]);
            r0.x += v.x; r0.y += v.y; r0.z += v.z; r0.w += v.w;
        }
        float inv = 1.f / fmaxf((float)(e - s), 1.f);
        acc.x += (r0.x+r1.x)*inv; acc.y += (r0.y+r1.y)*inv;
        acc.z += (r0.z+r1.z)*inv; acc.w += (r0.w+r1.w)*inv;
    }
    *(float4*)&g_ent1[d*DIMF + lane*4] = acc;
}

// ---------------- hop2 (items) + item_out + packed user row + item_mean -----
__global__ void k_hop2_items(const float* __restrict__ cf, float* __restrict__ out_item) {
    __shared__ float s_im[DIMF];
    int tid = threadIdx.x;
    if (tid < DIMF) s_im[tid] = 0.f;
    __syncthreads();

    int d = blockIdx.x*(blockDim.x/32) + (tid >> 5);
    int lane = tid & 31;
    if (d < N_ITEMS) {
        float4 acc = make_float4(0.f,0.f,0.f,0.f);
        #pragma unroll
        for (int r = 0; r < N_REL; r++) {
            int base = kgrow(d, r);
            int s = __ldg(&g_rowptr[base]), e = __ldg(&g_rowptr[base+1]);
            float4 r0 = make_float4(0.f,0.f,0.f,0.f);
            float4 r1 = make_float4(0.f,0.f,0.f,0.f);
            int j = s;
            for (; j + 1 < e; j += 2) {
                int c0 = __ldg(&g_col[j]), c1 = __ldg(&g_col[j+1]);
                float4 v0 = __ldg((const float4*)&g_ent1[c0*DIMF + lane*4]);
                float4 v1 = __ldg((const float4*)&g_ent1[c1*DIMF + lane*4]);
                r0.x += v0.x; r0.y += v0.y; r0.z += v0.z; r0.w += v0.w;
                r1.x += v1.x; r1.y += v1.y; r1.z += v1.z; r1.w += v1.w;
            }
            if (j < e) {
                float4 v = __ldg((const float4*)&g_ent1[__ldg(&g_col[j])*DIMF + lane*4]);
                r0.x += v.x; r0.y += v.y; r0.z += v.z; r0.w += v.w;
            }
            float inv = 1.f / fmaxf((float)(e - s), 1.f);
            acc.x += (r0.x+r1.x)*inv; acc.y += (r0.y+r1.y)*inv;
            acc.z += (r0.z+r1.z)*inv; acc.w += (r0.w+r1.w)*inv;
        }
        int o = d*DIMF + lane*4;
        const float4 e0 = *(const float4*)&g_ent0[o];
        const float4 e1 = *(const float4*)&g_ent1[o];
        float4 res;
        res.x = acc.x + e0.x + e1.x;
        res.y = acc.y + e0.y + e1.y;
        res.z = acc.z + e0.z + e1.z;
        res.w = acc.w + e0.w + e1.w;
        const float4 c = __ldg((const float4*)&cf[(size_t)(N_USERS + d)*DIMF + lane*4]);
        // fp32 item output
        float4 oi;
        oi.x = res.x + c.x; oi.y = res.y + c.y; oi.z = res.z + c.z; oi.w = res.w + c.w;
        *(float4*)&out_item[o] = oi;
        // packed user row: entres fp32 (feeds attention -> must be fp32),
        // item_cf fp16 (additive only -> fp16 safe)
        float* row = &g_urow[(size_t)d*ROWF];
        *(float4*)&row[lane*4] = res;
        sth4((__half*)&row[DIMF] + lane*4, c);
        // item_mean partial
        atomicAdd(&s_im[lane*4 + 0], res.x);
        atomicAdd(&s_im[lane*4 + 1], res.y);
        atomicAdd(&s_im[lane*4 + 2], res.z);
        atomicAdd(&s_im[lane*4 + 3], res.w);
    }
    __syncthreads();
    if (tid < DIMF) atomicAdd(&g_imean[tid], s_im[tid] * (1.f / N_ITEMS));
}

// ---------------- user aggregation + fused attention epilogue ---------------
__global__ void k_user(const float* __restrict__ cf, float* __restrict__ out_user) {
    int u = blockIdx.x*(blockDim.x/32) + (threadIdx.x >> 5);
    if (u >= N_USERS) return;
    int lane = threadIdx.x & 31;
    int base = KG_CNT + u;
    int s = __ldg(&g_rowptr[base]), e = __ldg(&g_rowptr[base+1]);
    float4 a0 = make_float4(0.f,0.f,0.f,0.f);
    float4 a1 = make_float4(0.f,0.f,0.f,0.f);
    float4 b0 = make_float4(0.f,0.f,0.f,0.f);
    float4 b1 = make_float4(0.f,0.f,0.f,0.f);
    int j = s;
    for (; j + 1 < e; j += 2) {
        const float* row0 = &g_urow[(size_t)__ldg(&g_col[j])  *ROWF];
        const float* row1 = &g_urow[(size_t)__ldg(&g_col[j+1])*ROWF];
        float4 x0 = __ldg((const float4*)&row0[lane*4]);
        float4 x1 = __ldg((const float4*)&row1[lane*4]);
        float4 y0 = ldh4((const __half*)&row0[DIMF] + lane*4);
        float4 y1 = ldh4((const __half*)&row1[DIMF] + lane*4);
        a0.x += x0.x; a0.y += x0.y; a0.z += x0.z; a0.w += x0.w;
        a1.x += x1.x; a1.y += x1.y; a1.z += x1.z; a1.w += x1.w;
        b0.x += y0.x; b0.y += y0.y; b0.z += y0.z; b0.w += y0.w;
        b1.x += y1.x; b1.y += y1.y; b1.z += y1.z; b1.w += y1.w;
    }
    if (j < e) {
        const float* row0 = &g_urow[(size_t)__ldg(&g_col[j])*ROWF];
        float4 x0 = __ldg((const float4*)&row0[lane*4]);
        float4 y0 = ldh4((const __half*)&row0[DIMF] + lane*4);
        a0.x += x0.x; a0.y += x0.y; a0.z += x0.z; a0.w += x0.w;
        b0.x += y0.x; b0.y += y0.y; b0.z += y0.z; b0.w += y0.w;
    }
    float inv = 1.f / fmaxf((float)(e - s), 1.f);
    float4 uf  = make_float4((a0.x+a1.x)*inv, (a0.y+a1.y)*inv, (a0.z+a1.z)*inv, (a0.w+a1.w)*inv);
    float4 uf0 = make_float4((b0.x+b1.x)*inv, (b0.y+b1.y)*inv, (b0.z+b1.z)*inv, (b0.w+b1.w)*inv);
    const float4 ucf = __ldg((const float4*)&cf[(size_t)u*DIMF + lane*4]);
    const float4 im  = *(const float4*)&g_imean[lane*4];

    float ua = uf.x*ucf.x + uf.y*ucf.y + uf.z*ucf.z + uf.w*ucf.w;
    float ma = im.x*ucf.x + im.y*ucf.y + im.z*ucf.z + im.w*ucf.w;
    ua += __shfl_xor_sync(0xffffffffu, ua, 1);
    ua += __shfl_xor_sync(0xffffffffu, ua, 2);
    ma += __shfl_xor_sync(0xffffffffu, ma, 1);
    ma += __shfl_xor_sync(0xffffffffu, ma, 2);
    ua = fmaxf(ua, 0.f) + 1e-10f;
    ma = fmaxf(ma, 0.f) + 1e-8f;
    float att = fmaxf(ua/ma - 1.f, 0.f) + 0.01f;   // K_ATT = 1.0
    float score = tanhf(att);

    float4 o;
    o.x = score*uf.x + uf0.x + ucf.x;
    o.y = score*uf.y + uf0.y + ucf.y;
    o.z = score*uf.z + uf0.z + ucf.z;
    o.w = score*uf.w + uf0.w + ucf.w;
    *(float4*)&out_user[(size_t)u*DIMF + lane*4] = o;
}

// ---------------- launch ----------------------------------------------------
extern "C" void kernel_launch(void* const* d_in, const int* in_sizes, int n_in,
                              void* d_out, int out_size) {
    const float* all_embed    = (const float*)d_in[0];
    const float* all_embed_cf = (const float*)d_in[1];
    const int*   kg_src       = (const int*)d_in[2];
    const int*   kg_dst       = (const int*)d_in[3];
    const int*   ui_src_item  = (const int*)d_in[4];
    const int*   ui_dst_user  = (const int*)d_in[5];
    float* out = (float*)d_out;
    float* out_item = out;                        // [N_ITEMS, 128]
    float* out_user = out + (size_t)N_ITEMS*DIMF; // [N_USERS, 128]

    const int T = 256;
    // CSR build
    k_zero<<<1024, T>>>();
    k_count<<<(TOT_EDGE + T - 1)/T, T>>>(kg_dst, ui_dst_user);
    k_scan1<<<NBLK, SCAN_B>>>();
    k_scan2<<<1, SCAN_B>>>();
    k_scan3<<<(TOT_CNT + T)/T, T>>>();
    k_fill<<<(TOT_EDGE + T - 1)/T, T>>>(kg_src, kg_dst, ui_src_item, ui_dst_user);

    // KG propagation
    int entWarpBlocks  = (N_ENT   + (T/32) - 1) / (T/32);
    int itemWarpBlocks = (N_ITEMS + (T/32) - 1) / (T/32);
    k_layer0<<<entWarpBlocks, T>>>(all_embed);
    k_hop1<<<entWarpBlocks, T>>>();
    k_hop2_items<<<itemWarpBlocks, T>>>(all_embed_cf, out_item);

    // user epilogue
    int userWarpBlocks = (N_USERS + (T/32) - 1) / (T/32);
    k_user<<<userWarpBlocks, T>>>(all_embed_cf, out_user);
}

// round 7
// speedup vs baseline: 1.6691x; 1.0354x over previous
#include <cuda_runtime.h>
#include <cuda_fp16.h>

#define N_USERS 50000
#define N_ITEMS 30000
#define N_ENT   100000
#define N_REL   8
#define E_KG    250000
#define E_UI    1000000
#define DIMF    128
#define ROWF    192      /* packed user row: 128 fp32 + 128 fp16 = 192 float slots */
#define KG_CNT  (N_REL*N_ENT)
#define TOT_CNT (KG_CNT + N_USERS)
#define KG_EDGE (N_REL*E_KG)
#define TOT_EDGE (KG_EDGE + E_UI)
#define SCAN_B  1024
#define NBLK    ((TOT_CNT + SCAN_B - 1)/SCAN_B)

// ---------------- scratch (static device globals; no allocation) ------------
__device__ float g_ent0[(size_t)N_ENT*DIMF];      // 51.2 MB fp32
__device__ float g_ent1[(size_t)N_ENT*DIMF];      // 51.2 MB fp32
__device__ float g_urow[(size_t)N_ITEMS*ROWF];    // 23.0 MB packed user rows
__device__ float g_w[KG_EDGE];                    // 8 MB per-edge 1/deg weights
__device__ int   g_cnt[TOT_CNT];
__device__ int   g_rowptr[TOT_CNT+1];
__device__ int   g_cursor[TOT_CNT];
__device__ int   g_col[TOT_EDGE];
__device__ int   g_bsum[NBLK];
__device__ float g_imean[DIMF];

__device__ __forceinline__ int kgrow(int d, int r) { return d*N_REL + r; }

__device__ __forceinline__ float4 ldh4(const __half* p) {
    uint2 u = __ldg((const uint2*)p);
    __half2 a = *(__half2*)&u.x, b = *(__half2*)&u.y;
    float2 f0 = __half22float2(a), f1 = __half22float2(b);
    return make_float4(f0.x, f0.y, f1.x, f1.y);
}
__device__ __forceinline__ void sth4(__half* p, float4 v) {
    __half2 a = __floats2half2_rn(v.x, v.y);
    __half2 b = __floats2half2_rn(v.z, v.w);
    uint2 u; u.x = *(unsigned*)&a; u.y = *(unsigned*)&b;
    *(uint2*)p = u;
}

// ---------------- CSR build -------------------------------------------------
__global__ void k_zero() {
    int i = blockIdx.x*blockDim.x + threadIdx.x;
    for (int t = i; t < TOT_CNT; t += gridDim.x*blockDim.x) g_cnt[t] = 0;
    if (i < DIMF) g_imean[i] = 0.f;
}

__global__ void k_count(const int* __restrict__ kg_dst, const int* __restrict__ ui_dst) {
    int tid = blockIdx.x*blockDim.x + threadIdx.x;
    if (tid < KG_EDGE) {
        int r = tid / E_KG;
        atomicAdd(&g_cnt[kgrow(__ldg(&kg_dst[tid]), r)], 1);
    } else if (tid < TOT_EDGE) {
        atomicAdd(&g_cnt[KG_CNT + __ldg(&ui_dst[tid - KG_EDGE])], 1);
    }
}

__global__ void k_scan1() {
    __shared__ int sh[SCAN_B];
    int i = blockIdx.x*SCAN_B + threadIdx.x;
    int v = (i < TOT_CNT) ? g_cnt[i] : 0;
    sh[threadIdx.x] = v;
    __syncthreads();
    #pragma unroll
    for (int off = 1; off < SCAN_B; off <<= 1) {
        int t = (threadIdx.x >= off) ? sh[threadIdx.x - off] : 0;
        __syncthreads();
        sh[threadIdx.x] += t;
        __syncthreads();
    }
    if (i < TOT_CNT) g_rowptr[i] = sh[threadIdx.x] - v;
    if (threadIdx.x == SCAN_B-1) g_bsum[blockIdx.x] = sh[SCAN_B-1];
}

__global__ void k_scan2() {
    __shared__ int sh[SCAN_B];
    int t = threadIdx.x;
    int v = (t < NBLK) ? g_bsum[t] : 0;
    sh[t] = v;
    __syncthreads();
    #pragma unroll
    for (int off = 1; off < SCAN_B; off <<= 1) {
        int u = (t >= off) ? sh[t - off] : 0;
        __syncthreads();
        sh[t] += u;
        __syncthreads();
    }
    if (t < NBLK) g_bsum[t] = sh[t] - v;
}

// scan finalize + per-edge weight fill (weights only for KG rows)
__global__ void k_scan3() {
    int i = blockIdx.x*blockDim.x + threadIdx.x;
    if (i < TOT_CNT) {
        int v = g_rowptr[i] + g_bsum[i / SCAN_B];
        g_rowptr[i] = v;
        g_cursor[i] = v;
        if (i < KG_CNT) {
            int deg = g_cnt[i];
            float w = 1.f / (float)(deg > 1 ? deg : 1);
            for (int j = 0; j < deg; j++) g_w[v + j] = w;
        }
    }
    if (i == TOT_CNT) g_rowptr[TOT_CNT] = TOT_EDGE;
}

__global__ void k_fill(const int* __restrict__ kg_src, const int* __restrict__ kg_dst,
                       const int* __restrict__ ui_src, const int* __restrict__ ui_dst) {
    int tid = blockIdx.x*blockDim.x + threadIdx.x;
    if (tid < KG_EDGE) {
        int r = tid / E_KG;
        int pos = atomicAdd(&g_cursor[kgrow(__ldg(&kg_dst[tid]), r)], 1);
        g_col[pos] = __ldg(&kg_src[tid]);
    } else if (tid < TOT_EDGE) {
        int t = tid - KG_EDGE;
        int pos = atomicAdd(&g_cursor[KG_CNT + __ldg(&ui_dst[t])], 1);
        g_col[pos] = __ldg(&ui_src[t]);
    }
}

// ---------------- layer 0 ----------------------------------------------------
__global__ void k_layer0(const float* __restrict__ all_embed) {
    int d = blockIdx.x*(blockDim.x/32) + (threadIdx.x >> 5);
    if (d >= N_ENT) return;
    int lane = threadIdx.x & 31;
    int dim  = lane & 15;
    int half = lane >> 4;
    #pragma unroll
    for (int r = 0; r < N_REL; r++) {
        int base = kgrow(d, r);
        int s = __ldg(&g_rowptr[base]), e = __ldg(&g_rowptr[base+1]);
        float acc = 0.f;
        for (int j = s + half; j < e; j += 2)
            acc += __ldg(&all_embed[__ldg(&g_col[j])*DIMF + r*16 + dim]);
        acc += __shfl_xor_sync(0xffffffffu, acc, 16);
        if (half == 0)
            g_ent0[d*DIMF + r*16 + dim] = acc / fmaxf((float)(e - s), 1.f);
    }
}

// ---- flat weighted KG gather: acc = sum_{j in [s,e)} w[j]*src[col[j]] ------
__device__ __forceinline__ float4 kg_gather(const float* __restrict__ src,
                                            int s, int e, int lane) {
    float4 a0 = make_float4(0.f,0.f,0.f,0.f);
    float4 a1 = make_float4(0.f,0.f,0.f,0.f);
    int j = s;
    for (; j + 3 < e; j += 4) {
        int   c0 = __ldg(&g_col[j]),   c1 = __ldg(&g_col[j+1]);
        int   c2 = __ldg(&g_col[j+2]), c3 = __ldg(&g_col[j+3]);
        float w0 = __ldg(&g_w[j]),     w1 = __ldg(&g_w[j+1]);
        float w2 = __ldg(&g_w[j+2]),   w3 = __ldg(&g_w[j+3]);
        float4 v0 = __ldg((const float4*)&src[c0*DIMF + lane*4]);
        float4 v1 = __ldg((const float4*)&src[c1*DIMF + lane*4]);
        float4 v2 = __ldg((const float4*)&src[c2*DIMF + lane*4]);
        float4 v3 = __ldg((const float4*)&src[c3*DIMF + lane*4]);
        a0.x += w0*v0.x; a0.y += w0*v0.y; a0.z += w0*v0.z; a0.w += w0*v0.w;
        a1.x += w1*v1.x; a1.y += w1*v1.y; a1.z += w1*v1.z; a1.w += w1*v1.w;
        a0.x += w2*v2.x; a0.y += w2*v2.y; a0.z += w2*v2.z; a0.w += w2*v2.w;
        a1.x += w3*v3.x; a1.y += w3*v3.y; a1.z += w3*v3.z; a1.w += w3*v3.w;
    }
    for (; j < e; j++) {
        int c = __ldg(&g_col[j]);
        float w = __ldg(&g_w[j]);
        float4 v = __ldg((const float4*)&src[c*DIMF + lane*4]);
        a0.x += w*v.x; a0.y += w*v.y; a0.z += w*v.z; a0.w += w*v.w;
    }
    return make_float4(a0.x+a1.x, a0.y+a1.y, a0.z+a1.z, a0.w+a1.w);
}

// ---------------- hop1: ent1[d] = sum_r mean_r(ent0[src]) --------------------
__global__ void k_hop1() {
    int d = blockIdx.x*(blockDim.x/32) + (threadIdx.x >> 5);
    if (d >= N_ENT) return;
    int lane = threadIdx.x & 31;
    int s = __ldg(&g_rowptr[d*N_REL]);
    int e = __ldg(&g_rowptr[(d+1)*N_REL]);
    float4 acc = kg_gather(g_ent0, s, e, lane);
    *(float4*)&g_ent1[d*DIMF + lane*4] = acc;
}

// ---------------- hop2 (items) + item_out + packed user row + item_mean -----
__global__ void k_hop2_items(const float* __restrict__ cf, float* __restrict__ out_item) {
    __shared__ float s_im[DIMF];
    int tid = threadIdx.x;
    if (tid < DIMF) s_im[tid] = 0.f;
    __syncthreads();

    int d = blockIdx.x*(blockDim.x/32) + (tid >> 5);
    int lane = tid & 31;
    if (d < N_ITEMS) {
        int s = __ldg(&g_rowptr[d*N_REL]);
        int e = __ldg(&g_rowptr[(d+1)*N_REL]);
        float4 acc = kg_gather(g_ent1, s, e, lane);
        int o = d*DIMF + lane*4;
        const float4 e0 = *(const float4*)&g_ent0[o];
        const float4 e1 = *(const float4*)&g_ent1[o];
        float4 res;
        res.x = acc.x + e0.x + e1.x;
        res.y = acc.y + e0.y + e1.y;
        res.z = acc.z + e0.z + e1.z;
        res.w = acc.w + e0.w + e1.w;
        const float4 c = __ldg((const float4*)&cf[(size_t)(N_USERS + d)*DIMF + lane*4]);
        float4 oi;
        oi.x = res.x + c.x; oi.y = res.y + c.y; oi.z = res.z + c.z; oi.w = res.w + c.w;
        *(float4*)&out_item[o] = oi;
        float* row = &g_urow[(size_t)d*ROWF];
        *(float4*)&row[lane*4] = res;
        sth4((__half*)&row[DIMF] + lane*4, c);
        atomicAdd(&s_im[lane*4 + 0], res.x);
        atomicAdd(&s_im[lane*4 + 1], res.y);
        atomicAdd(&s_im[lane*4 + 2], res.z);
        atomicAdd(&s_im[lane*4 + 3], res.w);
    }
    __syncthreads();
    if (tid < DIMF) atomicAdd(&g_imean[tid], s_im[tid] * (1.f / N_ITEMS));
}

// ---------------- user aggregation + fused attention epilogue ---------------
__global__ void k_user(const float* __restrict__ cf, float* __restrict__ out_user) {
    int u = blockIdx.x*(blockDim.x/32) + (threadIdx.x >> 5);
    if (u >= N_USERS) return;
    int lane = threadIdx.x & 31;
    int base = KG_CNT + u;
    int s = __ldg(&g_rowptr[base]), e = __ldg(&g_rowptr[base+1]);
    float4 a0 = make_float4(0.f,0.f,0.f,0.f);
    float4 a1 = make_float4(0.f,0.f,0.f,0.f);
    float4 b0 = make_float4(0.f,0.f,0.f,0.f);
    float4 b1 = make_float4(0.f,0.f,0.f,0.f);
    int j = s;
    for (; j + 3 < e; j += 4) {
        const float* r0 = &g_urow[(size_t)__ldg(&g_col[j])  *ROWF];
        const float* r1 = &g_urow[(size_t)__ldg(&g_col[j+1])*ROWF];
        const float* r2 = &g_urow[(size_t)__ldg(&g_col[j+2])*ROWF];
        const float* r3 = &g_urow[(size_t)__ldg(&g_col[j+3])*ROWF];
        float4 x0 = __ldg((const float4*)&r0[lane*4]);
        float4 x1 = __ldg((const float4*)&r1[lane*4]);
        float4 x2 = __ldg((const float4*)&r2[lane*4]);
        float4 x3 = __ldg((const float4*)&r3[lane*4]);
        float4 y0 = ldh4((const __half*)&r0[DIMF] + lane*4);
        float4 y1 = ldh4((const __half*)&r1[DIMF] + lane*4);
        float4 y2 = ldh4((const __half*)&r2[DIMF] + lane*4);
        float4 y3 = ldh4((const __half*)&r3[DIMF] + lane*4);
        a0.x += x0.x; a0.y += x0.y; a0.z += x0.z; a0.w += x0.w;
        a1.x += x1.x; a1.y += x1.y; a1.z += x1.z; a1.w += x1.w;
        a0.x += x2.x; a0.y += x2.y; a0.z += x2.z; a0.w += x2.w;
        a1.x += x3.x; a1.y += x3.y; a1.z += x3.z; a1.w += x3.w;
        b0.x += y0.x; b0.y += y0.y; b0.z += y0.z; b0.w += y0.w;
        b1.x += y1.x; b1.y += y1.y; b1.z += y1.z; b1.w += y1.w;
        b0.x += y2.x; b0.y += y2.y; b0.z += y2.z; b0.w += y2.w;
        b1.x += y3.x; b1.y += y3.y; b1.z += y3.z; b1.w += y3.w;
    }
    for (; j < e; j++) {
        const float* r0 = &g_urow[(size_t)__ldg(&g_col[j])*ROWF];
        float4 x0 = __ldg((const float4*)&r0[lane*4]);
        float4 y0 = ldh4((const __half*)&r0[DIMF] + lane*4);
        a0.x += x0.x; a0.y += x0.y; a0.z += x0.z; a0.w += x0.w;
        b0.x += y0.x; b0.y += y0.y; b0.z += y0.z; b0.w += y0.w;
    }
    float inv = 1.f / fmaxf((float)(e - s), 1.f);
    float4 uf  = make_float4((a0.x+a1.x)*inv, (a0.y+a1.y)*inv, (a0.z+a1.z)*inv, (a0.w+a1.w)*inv);
    float4 uf0 = make_float4((b0.x+b1.x)*inv, (b0.y+b1.y)*inv, (b0.z+b1.z)*inv, (b0.w+b1.w)*inv);
    const float4 ucf = __ldg((const float4*)&cf[(size_t)u*DIMF + lane*4]);
    const float4 im  = *(const float4*)&g_imean[lane*4];

    float ua = uf.x*ucf.x + uf.y*ucf.y + uf.z*ucf.z + uf.w*ucf.w;
    float ma = im.x*ucf.x + im.y*ucf.y + im.z*ucf.z + im.w*ucf.w;
    ua += __shfl_xor_sync(0xffffffffu, ua, 1);
    ua += __shfl_xor_sync(0xffffffffu, ua, 2);
    ma += __shfl_xor_sync(0xffffffffu, ma, 1);
    ma += __shfl_xor_sync(0xffffffffu, ma, 2);
    ua = fmaxf(ua, 0.f) + 1e-10f;
    ma = fmaxf(ma, 0.f) + 1e-8f;
    float att = fmaxf(ua/ma - 1.f, 0.f) + 0.01f;   // K_ATT = 1.0
    float score = tanhf(att);

    float4 o;
    o.x = score*uf.x + uf0.x + ucf.x;
    o.y = score*uf.y + uf0.y + ucf.y;
    o.z = score*uf.z + uf0.z + ucf.z;
    o.w = score*uf.w + uf0.w + ucf.w;
    *(float4*)&out_user[(size_t)u*DIMF + lane*4] = o;
}

// ---------------- launch ----------------------------------------------------
extern "C" void kernel_launch(void* const* d_in, const int* in_sizes, int n_in,
                              void* d_out, int out_size) {
    const float* all_embed    = (const float*)d_in[0];
    const float* all_embed_cf = (const float*)d_in[1];
    const int*   kg_src       = (const int*)d_in[2];
    const int*   kg_dst       = (const int*)d_in[3];
    const int*   ui_src_item  = (const int*)d_in[4];
    const int*   ui_dst_user  = (const int*)d_in[5];
    float* out = (float*)d_out;
    float* out_item = out;                        // [N_ITEMS, 128]
    float* out_user = out + (size_t)N_ITEMS*DIMF; // [N_USERS, 128]

    const int T = 256;
    // CSR build
    k_zero<<<1024, T>>>();
    k_count<<<(TOT_EDGE + T - 1)/T, T>>>(kg_dst, ui_dst_user);
    k_scan1<<<NBLK, SCAN_B>>>();
    k_scan2<<<1, SCAN_B>>>();
    k_scan3<<<(TOT_CNT + T)/T, T>>>();
    k_fill<<<(TOT_EDGE + T - 1)/T, T>>>(kg_src, kg_dst, ui_src_item, ui_dst_user);

    // KG propagation
    int entWarpBlocks  = (N_ENT   + (T/32) - 1) / (T/32);
    int itemWarpBlocks = (N_ITEMS + (T/32) - 1) / (T/32);
    k_layer0<<<entWarpBlocks, T>>>(all_embed);
    k_hop1<<<entWarpBlocks, T>>>();
    k_hop2_items<<<itemWarpBlocks, T>>>(all_embed_cf, out_item);

    // user epilogue
    int userWarpBlocks = (N_USERS + (T/32) - 1) / (T/32);
    k_user<<<userWarpBlocks, T>>>(all_embed_cf, out_user);
}